// round 11
// baseline (speedup 1.0000x reference)
#include <cuda_runtime.h>
#include <cstdint>

#define N_GRAPHS 1024
#define N_NODES  65536
#define N_EDGES  262144
#define D        256
#define D_IN     768
#define D_HID    512
#define D_OUT    256

// Scratch (no allocations allowed)
__device__ float g_collected[N_GRAPHS * D_IN];
__device__ float g_hidden[N_GRAPHS * D_HID];
__device__ int   g_eoff[N_GRAPHS + 1];
__device__ int   g_noff[N_GRAPHS + 1];

// ---------------------------------------------------------------------------
// Kernel 0: one-shot boundary precompute (2050 parallel binary searches).
// ---------------------------------------------------------------------------
__global__ void bounds_kernel(const int* __restrict__ eids,
                              const int* __restrict__ nids)
{
    const int t = blockIdx.x * blockDim.x + threadIdx.x;
    if (t <= N_GRAPHS) {
        int lo = 0, hi = N_EDGES;
        while (lo < hi) {
            int m = (lo + hi) >> 1;
            if (eids[m] < t) lo = m + 1; else hi = m;
        }
        g_eoff[t] = lo;
    } else if (t <= 2 * N_GRAPHS + 1) {
        const int g = t - (N_GRAPHS + 1);
        int lo = 0, hi = N_NODES;
        while (lo < hi) {
            int m = (lo + hi) >> 1;
            if (nids[m] < g) lo = m + 1; else hi = m;
        }
        g_noff[g] = lo;
    }
}

// ---------------------------------------------------------------------------
// Kernel 1: segment sums + concat. 8 CTAs/graph, precomputed bounds.
// 256 threads = 32 row-lanes x 8 float4-cols. Shuffle + smem reduce.
// ---------------------------------------------------------------------------
__global__ __launch_bounds__(256) void collect_kernel(
    const float4* __restrict__ nodes,
    const float4* __restrict__ edges,
    const float4* __restrict__ globals_,
    float4* __restrict__ collected4)
{
    const int g     = blockIdx.x >> 3;
    const int chunk = blockIdx.x & 7;
    const int t     = threadIdx.x;
    const int c     = t & 7;
    const int rl    = t >> 3;
    const int lane  = t & 31;
    const int wid   = t >> 5;
    const int colf4 = chunk * 8 + c;

    __shared__ float4 red_e[8][8];
    __shared__ float4 red_n[8][8];

    const int elo = __ldg(&g_eoff[g]), ehi = __ldg(&g_eoff[g + 1]);
    const int nlo = __ldg(&g_noff[g]), nhi = __ldg(&g_noff[g + 1]);

    float4 eacc = make_float4(0.f, 0.f, 0.f, 0.f);
    #pragma unroll 8
    for (int r = elo + rl; r < ehi; r += 32) {
        float4 v = __ldcs(&edges[(size_t)r * (D / 4) + colf4]);
        eacc.x += v.x; eacc.y += v.y; eacc.z += v.z; eacc.w += v.w;
    }
    float4 nacc = make_float4(0.f, 0.f, 0.f, 0.f);
    #pragma unroll 4
    for (int r = nlo + rl; r < nhi; r += 32) {
        float4 v = __ldcs(&nodes[(size_t)r * (D / 4) + colf4]);
        nacc.x += v.x; nacc.y += v.y; nacc.z += v.z; nacc.w += v.w;
    }

    #pragma unroll
    for (int s = 8; s <= 16; s <<= 1) {
        eacc.x += __shfl_xor_sync(0xffffffffu, eacc.x, s);
        eacc.y += __shfl_xor_sync(0xffffffffu, eacc.y, s);
        eacc.z += __shfl_xor_sync(0xffffffffu, eacc.z, s);
        eacc.w += __shfl_xor_sync(0xffffffffu, eacc.w, s);
        nacc.x += __shfl_xor_sync(0xffffffffu, nacc.x, s);
        nacc.y += __shfl_xor_sync(0xffffffffu, nacc.y, s);
        nacc.z += __shfl_xor_sync(0xffffffffu, nacc.z, s);
        nacc.w += __shfl_xor_sync(0xffffffffu, nacc.w, s);
    }
    if (lane < 8) { red_e[wid][lane] = eacc; red_n[wid][lane] = nacc; }
    __syncthreads();

    if (t < 8) {
        float4 s = red_e[0][t];
        #pragma unroll
        for (int i = 1; i < 8; ++i) {
            float4 v = red_e[i][t];
            s.x += v.x; s.y += v.y; s.z += v.z; s.w += v.w;
        }
        collected4[(size_t)g * (D_IN / 4) + chunk * 8 + t] = s;
    } else if (t < 16) {
        const int cc = t - 8;
        float4 s = red_n[0][cc];
        #pragma unroll
        for (int i = 1; i < 8; ++i) {
            float4 v = red_n[i][cc];
            s.x += v.x; s.y += v.y; s.z += v.z; s.w += v.w;
        }
        collected4[(size_t)g * (D_IN / 4) + (D / 4) + chunk * 8 + cc] = s;
    } else if (t < 24) {
        const int cc = t - 16;
        collected4[(size_t)g * (D_IN / 4) + 2 * (D / 4) + chunk * 8 + cc] =
            globals_[(size_t)g * (D / 4) + chunk * 8 + cc];
    }
}

// ---------------------------------------------------------------------------
// Kernel 2: TF32 MMA GEMM, 256 threads / 8 warps, BM=BN=64, BK=32.
// cp.async double-buffered smem (f32), ONE __syncthreads per K-iter,
// cvt to tf32 at fragment-load time. Warp tile 32x16 (2x4 warp grid).
// ---------------------------------------------------------------------------
__device__ __forceinline__ unsigned f2tf32(float x) {
    unsigned r;
    asm("cvt.rna.tf32.f32 %0, %1;" : "=r"(r) : "f"(x));
    return r;
}

__device__ __forceinline__ void mma_tf32(float (&c)[4],
                                         const unsigned (&a)[4],
                                         const unsigned (&b)[2]) {
    asm volatile(
        "mma.sync.aligned.m16n8k8.row.col.f32.tf32.tf32.f32 "
        "{%0,%1,%2,%3}, {%4,%5,%6,%7}, {%8,%9}, {%0,%1,%2,%3};\n"
        : "+f"(c[0]), "+f"(c[1]), "+f"(c[2]), "+f"(c[3])
        : "r"(a[0]), "r"(a[1]), "r"(a[2]), "r"(a[3]),
          "r"(b[0]), "r"(b[1]));
}

__device__ __forceinline__ void cp_async16(void* smem_dst, const void* gmem_src) {
    unsigned s = (unsigned)__cvta_generic_to_shared(smem_dst);
    asm volatile("cp.async.cg.shared.global [%0], [%1], 16;\n"
                 :: "r"(s), "l"(gmem_src));
}

template <bool RELU>
__global__ __launch_bounds__(256) void mma_gemm(
    const float* __restrict__ A,
    const float* __restrict__ B,
    const float* __restrict__ bias,
    float* __restrict__ C,
    int M, int N, int K)
{
    constexpr int BM = 64, BN = 64, BK = 32;
    constexpr int AS = BK + 4;   // row stride (floats): 36 -> 144B, 16B-aligned
    constexpr int BS = BN + 8;   // row stride: 72 -> 288B, 16B-aligned
    __shared__ float As[2][BM][AS];
    __shared__ float Bs[2][BK][BS];

    const int tid  = threadIdx.x;
    const int wid  = tid >> 5;
    const int lane = tid & 31;
    const int gid  = lane >> 2;
    const int tig  = lane & 3;
    const int m0 = blockIdx.y * BM;
    const int n0 = blockIdx.x * BN;
    const int wm = (wid & 1) * 32;        // 2 warps along m
    const int wn = (wid >> 1) * 16;       // 4 warps along n

    float c[2][2][4];
    #pragma unroll
    for (int i = 0; i < 2; ++i)
        #pragma unroll
        for (int j = 0; j < 2; ++j)
            #pragma unroll
            for (int q = 0; q < 4; ++q) c[i][j][q] = 0.f;

    auto load_stage = [&](int buf, int k0) {
        // A: 64x32 f32 = 512 float4, 2 per thread
        #pragma unroll
        for (int p = 0; p < 2; ++p) {
            int idx = tid + p * 256;
            int r = idx >> 3, c4 = idx & 7;
            cp_async16(&As[buf][r][c4 * 4],
                       &A[(size_t)(m0 + r) * K + k0 + c4 * 4]);
        }
        // B: 32x64 f32 = 512 float4, 2 per thread
        #pragma unroll
        for (int p = 0; p < 2; ++p) {
            int idx = tid + p * 256;
            int r = idx >> 4, c4 = idx & 15;
            cp_async16(&Bs[buf][r][c4 * 4],
                       &B[(size_t)(k0 + r) * N + n0 + c4 * 4]);
        }
        asm volatile("cp.async.commit_group;\n" ::: "memory");
    };

    load_stage(0, 0);

    const int n_iter = K / BK;
    for (int it = 0; it < n_iter; ++it) {
        asm volatile("cp.async.wait_group 0;\n" ::: "memory");
        __syncthreads();   // stage ready; all threads done computing other buf
        const int buf = it & 1;
        if (it + 1 < n_iter) load_stage(buf ^ 1, (it + 1) * BK);

        #pragma unroll
        for (int ks = 0; ks < BK; ks += 8) {
            unsigned a[2][4], b[2][2];
            #pragma unroll
            for (int mt = 0; mt < 2; ++mt) {
                const int rb = wm + mt * 16 + gid;
                a[mt][0] = f2tf32(As[buf][rb][ks + tig]);
                a[mt][1] = f2tf32(As[buf][rb + 8][ks + tig]);
                a[mt][2] = f2tf32(As[buf][rb][ks + tig + 4]);
                a[mt][3] = f2tf32(As[buf][rb + 8][ks + tig + 4]);
            }
            #pragma unroll
            for (int nt = 0; nt < 2; ++nt) {
                const int cb = wn + nt * 8 + gid;
                b[nt][0] = f2tf32(Bs[buf][ks + tig][cb]);
                b[nt][1] = f2tf32(Bs[buf][ks + tig + 4][cb]);
            }
            #pragma unroll
            for (int mt = 0; mt < 2; ++mt)
                #pragma unroll
                for (int nt = 0; nt < 2; ++nt)
                    mma_tf32(c[mt][nt], a[mt], b[nt]);
        }
    }

    // Epilogue: bias (+ReLU)
    #pragma unroll
    for (int mt = 0; mt < 2; ++mt) {
        const int row = m0 + wm + mt * 16 + gid;
        #pragma unroll
        for (int nt = 0; nt < 2; ++nt) {
            const int col = n0 + wn + nt * 8 + 2 * tig;
            float2 bv = *reinterpret_cast<const float2*>(&bias[col]);
            float2 v0, v1;
            v0.x = c[mt][nt][0] + bv.x;
            v0.y = c[mt][nt][1] + bv.y;
            v1.x = c[mt][nt][2] + bv.x;
            v1.y = c[mt][nt][3] + bv.y;
            if (RELU) {
                v0.x = fmaxf(v0.x, 0.f); v0.y = fmaxf(v0.y, 0.f);
                v1.x = fmaxf(v1.x, 0.f); v1.y = fmaxf(v1.y, 0.f);
            }
            *reinterpret_cast<float2*>(&C[(size_t)row * N + col]) = v0;
            *reinterpret_cast<float2*>(&C[(size_t)(row + 8) * N + col]) = v1;
        }
    }
}

extern "C" void kernel_launch(void* const* d_in, const int* in_sizes, int n_in,
                              void* d_out, int out_size)
{
    const float* nodes    = (const float*)d_in[0];
    const float* edges    = (const float*)d_in[1];
    const float* globals_ = (const float*)d_in[2];
    const int*   node_ids = (const int*)d_in[3];
    const int*   edge_ids = (const int*)d_in[4];
    const float* W1       = (const float*)d_in[5];
    const float* b1       = (const float*)d_in[6];
    const float* W2       = (const float*)d_in[7];
    const float* b2       = (const float*)d_in[8];
    float* out = (float*)d_out;

    float* collected = nullptr;
    float* hidden = nullptr;
    cudaGetSymbolAddress((void**)&collected, g_collected);
    cudaGetSymbolAddress((void**)&hidden, g_hidden);

    // Phase 0: all segment boundaries, once
    bounds_kernel<<<(2 * (N_GRAPHS + 1) + 255) / 256, 256>>>(edge_ids, node_ids);

    // Phase 1: segment sums + concat
    collect_kernel<<<8 * N_GRAPHS, 256>>>(
        (const float4*)nodes, (const float4*)edges, (const float4*)globals_,
        (float4*)collected);

    // Phase 2: hidden = relu(collected @ W1 + b1)   [1024,768]@[768,512]
    {
        dim3 grid(D_HID / 64, N_GRAPHS / 64);   // 8 x 16 = 128 CTAs
        mma_gemm<true><<<grid, 256>>>(collected, W1, b1, hidden,
                                      N_GRAPHS, D_HID, D_IN);
    }
    // Phase 3: out = hidden @ W2 + b2               [1024,512]@[512,256]
    {
        dim3 grid(D_OUT / 64, N_GRAPHS / 64);   // 4 x 16 = 64 CTAs
        mma_gemm<false><<<grid, 256>>>(hidden, W2, b2, out,
                                       N_GRAPHS, D_OUT, D_HID);
    }
}